// round 16
// baseline (speedup 1.0000x reference)
#include <cuda_runtime.h>
#include <cstdint>
#include <math.h>

// Problem constants
#define BSZ   4
#define TLEN  2048
#define CDIM  1024
#define NHEAD 16
#define HDIM  64
#define MTOT  (BSZ * TLEN)          // 8192

// ---------------------------------------------------------------------------
// Scratch (device globals — no allocation allowed)
// ---------------------------------------------------------------------------
__device__ float g_q[BSZ * NHEAD * TLEN * HDIM];   // [b,h,t,d] raw
__device__ float g_k[BSZ * NHEAD * TLEN * HDIM];   // tf32-rounded
__device__ float g_v[BSZ * NHEAD * TLEN * HDIM];   // tf32-rounded
__device__ float g_att[BSZ * TLEN * CDIM];         // [b,t,c] tf32-rounded
__device__ float g_wT[4 * CDIM * CDIM];            // W^T, tf32-rounded
__device__ float g_xr[MTOT * CDIM];                // x, tf32-rounded

#define WT_PROJ_OFF (3 * CDIM * CDIM)

// ---------------------------------------------------------------------------
// Portable PTX helpers (sm_80+ only; harness targets plain sm_100)
// ---------------------------------------------------------------------------
__device__ __forceinline__ uint32_t smem_u32(const void* p) {
    uint32_t a;
    asm("{ .reg .u64 t; cvta.to.shared.u64 t, %1; cvt.u32.u64 %0, t; }" : "=r"(a) : "l"(p));
    return a;
}

#define CP_ASYNC16(dst, src) \
    asm volatile("cp.async.cg.shared.global [%0], [%1], 16;" :: "r"(dst), "l"(src))
#define CP_COMMIT() asm volatile("cp.async.commit_group;")
#define CP_WAIT(n)  asm volatile("cp.async.wait_group %0;" :: "n"(n))

__device__ __forceinline__ uint32_t swz(uint32_t off) { return off ^ ((off >> 3) & 0x70); }

__device__ __forceinline__ uint32_t f2tf32(float f) {
    uint32_t r;
    asm("cvt.rna.tf32.f32 %0, %1;" : "=r"(r) : "f"(f));
    return r;
}
__device__ __forceinline__ float rnd_tf32(float f) { return __uint_as_float(f2tf32(f)); }

// m16n8k8 tf32 mma, fp32 accumulate (sm_80+)
__device__ __forceinline__ void mma_tf32(float c[4],
                                         uint32_t a0, uint32_t a1, uint32_t a2, uint32_t a3,
                                         uint32_t b0, uint32_t b1) {
    asm volatile(
        "mma.sync.aligned.m16n8k8.row.col.f32.tf32.tf32.f32 "
        "{%0,%1,%2,%3}, {%4,%5,%6,%7}, {%8,%9}, {%0,%1,%2,%3};"
        : "+f"(c[0]), "+f"(c[1]), "+f"(c[2]), "+f"(c[3])
        : "r"(a0), "r"(a1), "r"(a2), "r"(a3), "r"(b0), "r"(b1));
}

// ---------------------------------------------------------------------------
// Elementwise pre-round of x to tf32 (hoists the GEMM A-side cvts)
// ---------------------------------------------------------------------------
__global__ __launch_bounds__(256)
void round_x(const float* __restrict__ in)
{
    const int i = blockIdx.x * 256 + threadIdx.x;      // float4 index
    float4 v = ((const float4*)in)[i];
    ((float4*)g_xr)[i] = make_float4(rnd_tf32(v.x), rnd_tf32(v.y),
                                     rnd_tf32(v.z), rnd_tf32(v.w));
}

// ---------------------------------------------------------------------------
// Weight transpose: out[c][r] = tf32(in[r][c])  (pre-rounded for the GEMMs)
// ---------------------------------------------------------------------------
__global__ __launch_bounds__(256)
void transpose_k(const float* __restrict__ in, int dst_off, int R, int C)
{
    __shared__ float t[32][33];
    const int c0 = blockIdx.x * 32, r0 = blockIdx.y * 32;
    const int tx = threadIdx.x, ty = threadIdx.y;
#pragma unroll
    for (int i = ty; i < 32; i += 8)
        t[i][tx] = in[(r0 + i) * C + c0 + tx];
    __syncthreads();
#pragma unroll
    for (int i = ty; i < 32; i += 8)
        g_wT[dst_off + (c0 + i) * R + r0 + tx] = rnd_tf32(t[tx][i]);
}

// ---------------------------------------------------------------------------
// tf32 mma.sync GEMM. Both operands arrive pre-rounded -> pure bit loads.
// MODE 0: A = g_xr; epilogue rounds K/V sections on store.
// MODE 1: A = g_att (pre-rounded by flash epilogue).
// ---------------------------------------------------------------------------
#define TK          32
#define STAGES      3
#define STAGE_BYTES 32768
#define STAGE_F     8192
#define SMEM_GEMM   (STAGES * STAGE_BYTES)

template <int MODE>
__device__ __forceinline__ void load_stage(const float* Ap, const float* Bt,
                                           uint32_t sb, int m0, int n0, int tid,
                                           int s, int k0)
{
    const uint32_t base = sb + s * STAGE_BYTES;
#pragma unroll
    for (int j = 0; j < 4; j++) {
        const int idx = tid + j * 256;
        const int r = idx >> 3, c = idx & 7;
        CP_ASYNC16(base + swz(r * 128 + c * 16), Ap + (m0 + r) * CDIM + k0 + c * 4);
    }
#pragma unroll
    for (int j = 0; j < 4; j++) {
        const int idx = tid + j * 256;
        const int r = idx >> 3, c = idx & 7;
        CP_ASYNC16(base + 16384 + swz(r * 128 + c * 16), Bt + (n0 + r) * CDIM + k0 + c * 4);
    }
}

template <int MODE>
__global__ __launch_bounds__(256, 2)
void tc_gemm(int bt_off,
             const float* __restrict__ bias,
             const float* __restrict__ bQ,
             const float* __restrict__ bK,
             const float* __restrict__ bV,
             float* __restrict__ Cout)
{
    extern __shared__ float smemf[];
    const uint32_t sb = smem_u32(smemf);
    const int tid  = threadIdx.x;
    const int lane = tid & 31;
    const int wid  = tid >> 5;
    const int gid  = lane >> 2;
    const int tig  = lane & 3;
    const int wm   = (wid & 3) * 32;
    const int wn   = (wid >> 2) * 64;

    const int m0 = blockIdx.y * 128;
    const int n0 = blockIdx.x * 128;

    const float* Ap = (MODE == 1) ? (const float*)g_att : (const float*)g_xr;
    const float* Bt = g_wT + bt_off;

    float acc[2][8][4];
#pragma unroll
    for (int mt = 0; mt < 2; mt++)
#pragma unroll
        for (int nt = 0; nt < 8; nt++)
#pragma unroll
            for (int j = 0; j < 4; j++) acc[mt][nt][j] = 0.0f;

    load_stage<MODE>(Ap, Bt, sb, m0, n0, tid, 0, 0);
    CP_COMMIT();
    load_stage<MODE>(Ap, Bt, sb, m0, n0, tid, 1, TK);
    CP_COMMIT();

    const int NIT = CDIM / TK;
    const int xr  = gid << 2;

    int slot = 0;
    for (int i = 0; i < NIT; i++) {
        CP_WAIT(1);
        __syncthreads();

        if (i + 2 < NIT)
            load_stage<MODE>(Ap, Bt, sb, m0, n0, tid, (i + 2) % STAGES, (i + 2) * TK);
        CP_COMMIT();

        const float* As = smemf + slot * STAGE_F;
        const float* Bs = As + 4096;

#pragma unroll
        for (int ks = 0; ks < 4; ks++) {
            const int c0 = ((ks * 8) + tig) ^ xr;
            const int c4 = c0 ^ 4;

            uint32_t a[2][4];
#pragma unroll
            for (int mt = 0; mt < 2; mt++) {
                const int r0 = wm + mt * 16 + gid;
                const int r1 = r0 + 8;
                a[mt][0] = __float_as_uint(As[r0 * 32 + c0]);
                a[mt][1] = __float_as_uint(As[r1 * 32 + c0]);
                a[mt][2] = __float_as_uint(As[r0 * 32 + c4]);
                a[mt][3] = __float_as_uint(As[r1 * 32 + c4]);
            }
#pragma unroll
            for (int nt = 0; nt < 8; nt++) {
                const int n = wn + nt * 8 + gid;
                const uint32_t b0 = __float_as_uint(Bs[n * 32 + c0]);
                const uint32_t b1 = __float_as_uint(Bs[n * 32 + c4]);
                mma_tf32(acc[0][nt], a[0][0], a[0][1], a[0][2], a[0][3], b0, b1);
                mma_tf32(acc[1][nt], a[1][0], a[1][1], a[1][2], a[1][3], b0, b1);
            }
        }
        slot = (slot + 1) % STAGES;
    }

#pragma unroll
    for (int mt = 0; mt < 2; mt++) {
#pragma unroll
        for (int half = 0; half < 2; half++) {
            const int row = m0 + wm + mt * 16 + gid + half * 8;
#pragma unroll
            for (int nt = 0; nt < 8; nt++) {
                const int col = n0 + wn + nt * 8 + tig * 2;
                float v0 = acc[mt][nt][half * 2 + 0] + bias[col];
                float v1 = acc[mt][nt][half * 2 + 1] + bias[col + 1];

                if (MODE == 1) {
                    *(float2*)&Cout[(size_t)row * CDIM + col] = make_float2(v0, v1);
                } else {
                    const int sec = col >> 10;
                    const int n2  = col & 1023;
                    const float* hb = (sec == 0) ? bQ : (sec == 1) ? bK : bV;
                    v0 += hb[n2];
                    v1 += hb[n2 + 1];
                    if (sec != 0) {           // K/V consumed plain-tf32: pre-round
                        v0 = rnd_tf32(v0);
                        v1 = rnd_tf32(v1);
                    }
                    const int h  = n2 >> 6, dd = n2 & 63;
                    const int b_ = row >> 11, t = row & (TLEN - 1);
                    float* base = (sec == 0) ? g_q : (sec == 1) ? g_k : g_v;
                    *(float2*)&base[(((size_t)(b_ * NHEAD + h) * TLEN) + t) * HDIM + dd] =
                        make_float2(v0, v1);
                }
            }
        }
    }
}

// ---------------------------------------------------------------------------
// Flash attention v9 = R15 with pair-permuted Q/K storage for LDS.64 loads.
// Q, K stored with column permutation pi(c) = ((c&3)<<1)|((c>>2)&1)|(c&~7)
// and row stride 72: fragment cols (kc, kc+4) become an adjacent float2.
// Bank math: stride 72 fl = 36 8B-units, 36 mod 16 = 4 -> 8B-bank =
// (4*gid + tig) mod 16 = exactly 2-way = clean LDS.64 two-phase.
// V (stride 72) and P (stride 68) unchanged. SMEM 72704 B -> 3 CTA/SM.
// All changes are pure layout: rel_err must stay bit-identical (5.908059e-4).
// ---------------------------------------------------------------------------
#define SQ2   72                    // Q/K/V row stride (floats)
#define SP    68                    // P row stride
#define OFQ   0
#define OFK   (64 * SQ2)            // 4608
#define OFV   (2 * 64 * SQ2)        // 9216
#define OFP   (3 * 64 * SQ2)        // 13824
#define FL_SMEM ((OFP + 64 * SP) * 4)   // 72704 bytes

__global__ __launch_bounds__(128, 2)
void flash_mma()
{
    extern __shared__ float sm[];
    float* Qs = sm + OFQ;      // [64][72] permuted, pre-scaled
    float* Ks = sm + OFK;      // [64][72] permuted, tf32 bits
    float* Vs = sm + OFV;      // [64][72] straight (Vs[key][dim]), tf32 bits
    float* Ps = sm + OFP;      // [64][68] straight, tf32 bits

    const int tid  = threadIdx.x;
    const int lane = tid & 31;
    const int wid  = tid >> 5;
    const int gid  = lane >> 2;
    const int tig  = lane & 3;
    const int wr0  = wid * 16;

    const int qt = (int)gridDim.x - 1 - (int)blockIdx.x;   // heavy tiles first
    const int h  = blockIdx.y;
    const int b  = blockIdx.z;
    const int bh = b * NHEAD + h;
    const int q0 = qt * 64;

    // Load Q tile (pre-scaled by 1/sqrt(d)), permuted: float4 at col c
    // (c = 0,4,..,60) scatters to base + {0,2,4,6}, base = (c&~7) + ((c>>2)&1).
    for (int idx = tid; idx < 64 * 16; idx += 128) {
        const int row = idx >> 4, c = (idx & 15) * 4;
        float4 v = *(const float4*)(g_q + ((size_t)bh * TLEN + q0 + row) * HDIM + c);
        float* dst = Qs + row * SQ2 + (c & ~7) + ((c >> 2) & 1);
        dst[0] = v.x * 0.125f;
        dst[2] = v.y * 0.125f;
        dst[4] = v.z * 0.125f;
        dst[6] = v.w * 0.125f;
    }

    float o[8][4];
#pragma unroll
    for (int nt = 0; nt < 8; nt++)
#pragma unroll
        for (int j = 0; j < 4; j++) o[nt][j] = 0.0f;
    float mrow[2] = {-1e30f, -1e30f};
    float lrow[2] = {0.0f, 0.0f};

    for (int kt = 0; kt <= qt; kt++) {
        __syncthreads();   // previous iteration done with Ks/Vs/Ps
        for (int idx = tid; idx < 64 * 16; idx += 128) {
            const int row = idx >> 4, c = (idx & 15) * 4;
            const size_t src = ((size_t)bh * TLEN + kt * 64 + row) * HDIM + c;
            float4 kv = *(const float4*)(g_k + src);
            float* kd = Ks + row * SQ2 + (c & ~7) + ((c >> 2) & 1);
            kd[0] = kv.x; kd[2] = kv.y; kd[4] = kv.z; kd[6] = kv.w;
            *(float4*)(Vs + row * SQ2 + c) = *(const float4*)(g_v + src);
        }
        __syncthreads();

        // ---- S = Q K^T (split A, pre-rounded B; LDS.64 fragment loads) ----
        float s[8][4];
#pragma unroll
        for (int nt = 0; nt < 8; nt++)
#pragma unroll
            for (int j = 0; j < 4; j++) s[nt][j] = 0.0f;

#pragma unroll 2
        for (int ks = 0; ks < 8; ks++) {
            const int off = ks * 8 + 2 * tig;     // permuted: (kc, kc+4) pair
            const float2 qa = *(const float2*)(Qs + (wr0 + gid) * SQ2 + off);
            const float2 qb = *(const float2*)(Qs + (wr0 + gid + 8) * SQ2 + off);
            float af[4] = {qa.x, qb.x, qa.y, qb.y};
            uint32_t ah[4], al[4];
#pragma unroll
            for (int j = 0; j < 4; j++) {
                ah[j] = f2tf32(af[j]);
                al[j] = f2tf32(af[j] - __uint_as_float(ah[j]));
            }
#pragma unroll
            for (int nt = 0; nt < 8; nt++) {
                const float2 kb = *(const float2*)(Ks + (nt * 8 + gid) * SQ2 + off);
                const uint32_t b0 = __float_as_uint(kb.x);
                const uint32_t b1 = __float_as_uint(kb.y);
                mma_tf32(s[nt], ah[0], ah[1], ah[2], ah[3], b0, b1);
                mma_tf32(s[nt], al[0], al[1], al[2], al[3], b0, b1);
            }
        }

        // Causal mask (only the diagonal tile)
        if (kt == qt) {
#pragma unroll
            for (int nt = 0; nt < 8; nt++) {
#pragma unroll
                for (int j = 0; j < 4; j++) {
                    const int col = nt * 8 + 2 * tig + (j & 1);
                    const int row = wr0 + gid + (j >> 1) * 8;
                    if (col > row) s[nt][j] = -1e30f;
                }
            }
        }

        // Row max over tile (quad reduction)
        float tmax[2] = {-1e30f, -1e30f};
#pragma unroll
        for (int nt = 0; nt < 8; nt++) {
            tmax[0] = fmaxf(tmax[0], fmaxf(s[nt][0], s[nt][1]));
            tmax[1] = fmaxf(tmax[1], fmaxf(s[nt][2], s[nt][3]));
        }
#pragma unroll
        for (int d = 1; d <= 2; d <<= 1) {
            tmax[0] = fmaxf(tmax[0], __shfl_xor_sync(0xFFFFFFFFu, tmax[0], d));
            tmax[1] = fmaxf(tmax[1], __shfl_xor_sync(0xFFFFFFFFu, tmax[1], d));
        }
        const float mnew0 = fmaxf(mrow[0], tmax[0]);
        const float mnew1 = fmaxf(mrow[1], tmax[1]);
        const float corr0 = __expf(mrow[0] - mnew0);
        const float corr1 = __expf(mrow[1] - mnew1);

        // p = exp(s - m); sums use exact p; store tf32-rounded p for PV
        float ps[2] = {0.0f, 0.0f};
#pragma unroll
        for (int nt = 0; nt < 8; nt++) {
            const float p0 = __expf(s[nt][0] - mnew0);
            const float p1 = __expf(s[nt][1] - mnew0);
            const float p2 = __expf(s[nt][2] - mnew1);
            const float p3 = __expf(s[nt][3] - mnew1);
            ps[0] += p0 + p1;
            ps[1] += p2 + p3;
            *(float2*)(Ps + (wr0 + gid) * SP + nt * 8 + 2 * tig) =
                make_float2(rnd_tf32(p0), rnd_tf32(p1));
            *(float2*)(Ps + (wr0 + gid + 8) * SP + nt * 8 + 2 * tig) =
                make_float2(rnd_tf32(p2), rnd_tf32(p3));
        }
#pragma unroll
        for (int d = 1; d <= 2; d <<= 1) {
            ps[0] += __shfl_xor_sync(0xFFFFFFFFu, ps[0], d);
            ps[1] += __shfl_xor_sync(0xFFFFFFFFu, ps[1], d);
        }
        lrow[0] = lrow[0] * corr0 + ps[0];
        lrow[1] = lrow[1] * corr1 + ps[1];
#pragma unroll
        for (int nt = 0; nt < 8; nt++) {
            o[nt][0] *= corr0; o[nt][1] *= corr0;
            o[nt][2] *= corr1; o[nt][3] *= corr1;
        }
        mrow[0] = mnew0;
        mrow[1] = mnew1;
        __syncwarp();   // P rows of this warp visible to the whole warp

        // ---- O += P V (all operands pre-rounded: pure LDS + mma) ----
#pragma unroll 2
        for (int ks = 0; ks < 8; ks++) {
            const int kc = ks * 8 + tig;
            const uint32_t A0 = __float_as_uint(Ps[(wr0 + gid) * SP + kc]);
            const uint32_t A1 = __float_as_uint(Ps[(wr0 + gid + 8) * SP + kc]);
            const uint32_t A2 = __float_as_uint(Ps[(wr0 + gid) * SP + kc + 4]);
            const uint32_t A3 = __float_as_uint(Ps[(wr0 + gid + 8) * SP + kc + 4]);
#pragma unroll
            for (int nt = 0; nt < 8; nt++) {
                const uint32_t B0 = __float_as_uint(Vs[kc * SQ2 + nt * 8 + gid]);
                const uint32_t B1 = __float_as_uint(Vs[(kc + 4) * SQ2 + nt * 8 + gid]);
                mma_tf32(o[nt], A0, A1, A2, A3, B0, B1);
            }
        }
    }

    // Epilogue: divide by l; store tf32-rounded (proj GEMM reads A as bits)
    const float inv0 = 1.0f / lrow[0];
    const float inv1 = 1.0f / lrow[1];
    const size_t r0 = (size_t)b * TLEN + q0 + wr0 + gid;
#pragma unroll
    for (int nt = 0; nt < 8; nt++) {
        const int col = h * HDIM + nt * 8 + 2 * tig;
        *(float2*)(g_att + r0 * CDIM + col) =
            make_float2(rnd_tf32(o[nt][0] * inv0), rnd_tf32(o[nt][1] * inv0));
        *(float2*)(g_att + (r0 + 8) * CDIM + col) =
            make_float2(rnd_tf32(o[nt][2] * inv1), rnd_tf32(o[nt][3] * inv1));
    }
}

// ---------------------------------------------------------------------------
// kernel_launch
// Inputs: 0:x 1:W_attn 2:b_attn 3:W_proj 4:b_proj 5:bQ 6:bK 7:bV
// ---------------------------------------------------------------------------
extern "C" void kernel_launch(void* const* d_in, const int* in_sizes, int n_in,
                              void* d_out, int out_size)
{
    const float* x      = (const float*)d_in[0];
    const float* W_attn = (const float*)d_in[1];
    const float* b_attn = (const float*)d_in[2];
    const float* W_proj = (const float*)d_in[3];
    const float* b_proj = (const float*)d_in[4];
    const float* bQ     = (const float*)d_in[5];
    const float* bK     = (const float*)d_in[6];
    const float* bV     = (const float*)d_in[7];
    float* out = (float*)d_out;

    cudaFuncSetAttribute(tc_gemm<0>, cudaFuncAttributeMaxDynamicSharedMemorySize, SMEM_GEMM);
    cudaFuncSetAttribute(tc_gemm<1>, cudaFuncAttributeMaxDynamicSharedMemorySize, SMEM_GEMM);
    cudaFuncSetAttribute(flash_mma, cudaFuncAttributeMaxDynamicSharedMemorySize, FL_SMEM);

    // 0) Pre-round x; transpose weights into K-major tf32 form
    {
        round_x<<<MTOT * CDIM / 1024, 256>>>(x);
        dim3 tb(32, 8);
        transpose_k<<<dim3(3 * CDIM / 32, CDIM / 32), tb>>>(W_attn, 0, CDIM, 3 * CDIM);
        transpose_k<<<dim3(CDIM / 32, CDIM / 32), tb>>>(W_proj, WT_PROJ_OFF, CDIM, CDIM);
    }

    // 1) QKV GEMM (tf32 mma.sync) + bias + head scatter (K/V pre-rounded)
    {
        dim3 grid(3 * CDIM / 128, MTOT / 128);   // (24, 64)
        tc_gemm<0><<<grid, 256, SMEM_GEMM>>>(0, b_attn, bQ, bK, bV, nullptr);
    }

    // 2) Causal flash attention (pair-permuted LDS.64 loads)
    {
        dim3 grid(TLEN / 64, NHEAD, BSZ);        // (32, 16, 4)
        flash_mma<<<grid, 128, FL_SMEM>>>();
    }

    // 3) Projection GEMM (tf32 mma.sync) + b_proj
    {
        dim3 grid(CDIM / 128, MTOT / 128);       // (8, 64)
        tc_gemm<1><<<grid, 256, SMEM_GEMM>>>(WT_PROJ_OFF, b_proj,
                                             nullptr, nullptr, nullptr, out);
    }
}